// round 10
// baseline (speedup 1.0000x reference)
#include <cuda_runtime.h>
#include <cuda_fp16.h>
#include <cstdint>
#include <math.h>

// Problem constants
#define BQ      4
#define NT      4096
#define CC      768
#define NHEADS  12
#define NPTS    4
#define HDIM    64
#define HIDDEN  3072
#define MROWS   (BQ*NT)          // 16384
#define SCALE_ATTN 0.125f        // 64^-0.5
#define QKVW    (3*CC)           // 2304

// ---------------- scratch (device globals; no cudaMalloc allowed) ----------
__device__ __half g_h[(size_t)MROWS * CC];          // ln out (fp16, GEMM A operand)
__device__ __half g_qkv[(size_t)MROWS * QKVW];      // qkv (fp16)
__device__ float  g_off[(size_t)MROWS * NHEADS * NPTS * 2];
__device__ __half g_attn[(size_t)MROWS * CC];       // attention output (fp16)
__device__ __half g_mlp[(size_t)MROWS * HIDDEN];    // gelu(fc1) (fp16)
// fp16 weight copies (converted once per launch)
__device__ __half g_wqkv[(size_t)QKVW * CC];
__device__ __half g_wproj[(size_t)CC * CC];
__device__ __half g_wfc1[(size_t)HIDDEN * CC];
__device__ __half g_wfc2[(size_t)CC * HIDDEN];
__device__ __half g_woff[(size_t)256 * CC];         // off_w padded 96 -> 256 rows
__device__ float  g_offb[256];                      // off_b padded

// ---------------- weight conversion fp32 -> fp16 ---------------------------
__global__ __launch_bounds__(256) void wconv_kernel(
    const float* __restrict__ src, __half* __restrict__ dst, int n4)
{
    int i = blockIdx.x * 256 + threadIdx.x;
    if (i < n4) {
        float4 v = ((const float4*)src)[i];
        __half2 h0 = __floats2half2_rn(v.x, v.y);
        __half2 h1 = __floats2half2_rn(v.z, v.w);
        ((uint2*)dst)[i] = make_uint2(*(uint32_t*)&h0, *(uint32_t*)&h1);
    }
}

// off_w [96,768] -> fp16 padded [256,768] (zeros beyond 96); off_b -> padded fp32
__global__ __launch_bounds__(256) void woffprep_kernel(
    const float* __restrict__ off_w, const float* __restrict__ off_b,
    __half* __restrict__ woff, float* __restrict__ offb)
{
    int i = blockIdx.x * 256 + threadIdx.x;   // over 256*768
    if (i < 256 * CC) {
        int r = i / CC;
        woff[i] = (r < 96) ? __float2half_rn(off_w[i]) : __float2half_rn(0.f);
    }
    if (i < 256) offb[i] = (i < 96) ? off_b[i] : 0.f;
}

// ---------------- LayerNorm: fp32 in -> fp16 out ---------------------------
__global__ __launch_bounds__(256) void layernorm_kernel(
    const float* __restrict__ x, const float* __restrict__ w,
    const float* __restrict__ b, __half* __restrict__ out)
{
    int row = blockIdx.x;
    int t = threadIdx.x;
    const float* xr = x + (size_t)row * CC;
    float v0 = xr[t], v1 = xr[t + 256], v2 = xr[t + 512];
    float s  = v0 + v1 + v2;
    float sq = v0*v0 + v1*v1 + v2*v2;

    __shared__ float sh[16];
    #pragma unroll
    for (int o = 16; o > 0; o >>= 1) {
        s  += __shfl_xor_sync(0xffffffffu, s,  o);
        sq += __shfl_xor_sync(0xffffffffu, sq, o);
    }
    int wid = t >> 5, lane = t & 31;
    if (lane == 0) { sh[wid] = s; sh[8 + wid] = sq; }
    __syncthreads();
    if (t == 0) {
        float ts = 0.f, tq = 0.f;
        #pragma unroll
        for (int i = 0; i < 8; i++) { ts += sh[i]; tq += sh[8 + i]; }
        sh[0] = ts; sh[8] = tq;
    }
    __syncthreads();
    float mean = sh[0] * (1.0f / CC);
    float var  = sh[8] * (1.0f / CC) - mean * mean;
    float rstd = rsqrtf(var + 1e-5f);
    __half* orow = out + (size_t)row * CC;
    orow[t]       = __float2half_rn((v0 - mean) * rstd * w[t]       + b[t]);
    orow[t + 256] = __float2half_rn((v1 - mean) * rstd * w[t + 256] + b[t + 256]);
    orow[t + 512] = __float2half_rn((v2 - mean) * rstd * w[t + 512] + b[t + 512]);
}

// ============================================================================
// FP16 mma.sync GEMM: C[M,N] = A[M,K] * W[N,K]^T + bias (+epilogue)
// Block tile 128x256x32, warp tile 64x64, mma.m16n8k16, cp.async dbl-buffered.
// M%128==0, (grid.x*256) cols processed, stores guarded by nvalid.
// EPI: 0 = bias, 1 = bias + exact GELU, 2 = bias + residual add
// ============================================================================
#define HSTR 40   // smem row stride in halves (32 + 8 pad) -> conflict-free u32 LDS
#define HS_A0 0        // 128*40 = 5120
#define HS_A1 5120
#define HS_B0 10240    // 256*40 = 10240
#define HS_B1 20480
#define HSM_BYTES ((20480 + 10240) * 2)   // 61440

__device__ __forceinline__ void cp_async16(void* smem_dst, const void* gmem_src) {
    uint32_t s = (uint32_t)__cvta_generic_to_shared(smem_dst);
    asm volatile("cp.async.cg.shared.global [%0], [%1], 16;\n" :: "r"(s), "l"(gmem_src));
}

template<int EPI, typename OutT>
__global__ __launch_bounds__(256) void hgemm_nt(
    const __half* __restrict__ A,           // [M, >=K], row stride lda
    int lda,
    const __half* __restrict__ Bw,          // [>=gridN, K], K contiguous
    const float* __restrict__ bias,
    const float* __restrict__ Res, int ldr,
    OutT* __restrict__ C, int ldc,
    int K, int nvalid)
{
    extern __shared__ __half smh[];

    const int t = threadIdx.x;
    const int rowTile = blockIdx.y * 128;
    const int colTile = blockIdx.x * 256;

    const int warp = t >> 5, lane = t & 31;
    const int wm = (warp & 1) * 64;        // 2 warps along M
    const int wn = (warp >> 1) * 64;       // 4 warps along N
    const int g  = lane >> 2;              // 0..7
    const int t4 = lane & 3;               // 0..3

    float acc[4][8][4];
    #pragma unroll
    for (int i = 0; i < 4; i++)
        #pragma unroll
        for (int j = 0; j < 8; j++)
            #pragma unroll
            for (int r = 0; r < 4; r++) acc[i][j][r] = 0.f;

    const int NK = K / 32;
    const int Abase[2] = {HS_A0, HS_A1};
    const int Bbase[2] = {HS_B0, HS_B1};

    auto load_tile = [&](int kt, int buf) {
        const int kk = kt * 32;
        #pragma unroll
        for (int i = 0; i < 2; i++) {
            int c = t + i * 256;
            int row = c >> 2, kc = (c & 3) * 8;
            cp_async16(&smh[Abase[buf] + row * HSTR + kc],
                       A + (size_t)(rowTile + row) * lda + kk + kc);
        }
        #pragma unroll
        for (int i = 0; i < 4; i++) {
            int c = t + i * 256;
            int row = c >> 2, kc = (c & 3) * 8;
            cp_async16(&smh[Bbase[buf] + row * HSTR + kc],
                       Bw + (size_t)(colTile + row) * K + kk + kc);
        }
        asm volatile("cp.async.commit_group;\n");
    };

    load_tile(0, 0);
    if (NK > 1) load_tile(1, 1);

    for (int kt = 0; kt < NK; kt++) {
        const int buf = kt & 1;
        if (kt + 1 < NK) asm volatile("cp.async.wait_group 1;\n");
        else             asm volatile("cp.async.wait_group 0;\n");
        __syncthreads();

        const __half* As = &smh[Abase[buf]];
        const __half* Bs = &smh[Bbase[buf]];

        #pragma unroll
        for (int ks = 0; ks < 2; ks++) {
            const int k0 = ks * 16;
            uint32_t afr[4][4];
            #pragma unroll
            for (int i = 0; i < 4; i++) {
                int rr = wm + i * 16 + g;
                afr[i][0] = *(const uint32_t*)&As[(rr    ) * HSTR + k0 + 2 * t4];
                afr[i][1] = *(const uint32_t*)&As[(rr + 8) * HSTR + k0 + 2 * t4];
                afr[i][2] = *(const uint32_t*)&As[(rr    ) * HSTR + k0 + 2 * t4 + 8];
                afr[i][3] = *(const uint32_t*)&As[(rr + 8) * HSTR + k0 + 2 * t4 + 8];
            }
            uint32_t bfr[8][2];
            #pragma unroll
            for (int j = 0; j < 8; j++) {
                int cc = wn + j * 8 + g;
                bfr[j][0] = *(const uint32_t*)&Bs[cc * HSTR + k0 + 2 * t4];
                bfr[j][1] = *(const uint32_t*)&Bs[cc * HSTR + k0 + 2 * t4 + 8];
            }
            #pragma unroll
            for (int i = 0; i < 4; i++)
                #pragma unroll
                for (int j = 0; j < 8; j++) {
                    asm volatile(
                        "mma.sync.aligned.m16n8k16.row.col.f32.f16.f16.f32 "
                        "{%0,%1,%2,%3}, {%4,%5,%6,%7}, {%8,%9}, {%0,%1,%2,%3};\n"
                        : "+f"(acc[i][j][0]), "+f"(acc[i][j][1]),
                          "+f"(acc[i][j][2]), "+f"(acc[i][j][3])
                        : "r"(afr[i][0]), "r"(afr[i][1]), "r"(afr[i][2]), "r"(afr[i][3]),
                          "r"(bfr[j][0]), "r"(bfr[j][1]));
                }
        }
        __syncthreads();

        if (kt + 2 < NK) load_tile(kt + 2, buf);
    }

    // epilogue: acc[i][j] -> rows {wm+i*16+g, +8}, cols {wn+j*8+2*t4, +1}
    #pragma unroll
    for (int i = 0; i < 4; i++) {
        #pragma unroll
        for (int half = 0; half < 2; half++) {
            int r = rowTile + wm + i * 16 + g + half * 8;
            OutT* crow = C + (size_t)r * ldc;
            const float* rrow = (EPI == 2) ? (Res + (size_t)r * ldr) : nullptr;
            #pragma unroll
            for (int j = 0; j < 8; j++) {
                int cg = colTile + wn + j * 8 + t4 * 2;
                if (cg >= nvalid) continue;          // nvalid even -> cg+1 ok
                float v0 = acc[i][j][half * 2 + 0] + bias[cg];
                float v1 = acc[i][j][half * 2 + 1] + bias[cg + 1];
                if (EPI == 1) {
                    v0 = 0.5f * v0 * (1.0f + erff(v0 * 0.70710678118654752f));
                    v1 = 0.5f * v1 * (1.0f + erff(v1 * 0.70710678118654752f));
                }
                if (EPI == 2) { v0 += rrow[cg]; v1 += rrow[cg + 1]; }
                if (sizeof(OutT) == 2) {
                    __half2 hv = __floats2half2_rn(v0, v1);
                    *(__half2*)((__half*)crow + cg) = hv;
                } else {
                    *(float2*)((float*)crow + cg) = make_float2(v0, v1);
                }
            }
        }
    }
}

// ---------------- deformable sampling + attention --------------------------
// 4 heads / 128-thr block; lane owns channels {2*lane, 2*lane+1} (half2)
__global__ __launch_bounds__(128) void attn_kernel(
    const __half* __restrict__ qkv,   // [M, 2304] fp16
    const float* __restrict__ off,    // [M, 96]
    const float* __restrict__ refp,   // [M, 2]
    __half* __restrict__ out,         // [M, 768] fp16
    const int* __restrict__ Hp, const int* __restrict__ Wp)
{
    int bn   = blockIdx.x;
    int head = blockIdx.y * 4 + (threadIdx.x >> 5);
    int lane = threadIdx.x & 31;
    int b = bn / NT;

    int H = *Hp, W = *Wp;
    float fW = (float)W, fH = (float)H;

    const __half2* q2p = (const __half2*)(qkv + (size_t)bn * QKVW + head * HDIM);
    float2 q = __half22float2(q2p[lane]);

    float ref0 = refp[(size_t)bn * 2 + 0];
    float ref1 = refp[(size_t)bn * 2 + 1];

    const float* offp = off + (size_t)bn * (NHEADS * NPTS * 2) + head * (NPTS * 2);

    float dots[NPTS];
    float sv0[NPTS], sv1[NPTS];

    #pragma unroll
    for (int p = 0; p < NPTS; p++) {
        float o0 = offp[p * 2 + 0];
        float o1 = offp[p * 2 + 1];
        float gx = 2.0f * (ref0 + o0 / fW) - 1.0f;
        float gy = 2.0f * (ref1 + o1 / fH) - 1.0f;
        float x = ((gx + 1.0f) * fW - 1.0f) * 0.5f;
        float y = ((gy + 1.0f) * fH - 1.0f) * 0.5f;
        float x0f = floorf(x), y0f = floorf(y);
        float wx = x - x0f, wy = y - y0f;
        int x0 = (int)x0f, y0 = (int)y0f;

        float cw[4] = {(1.f - wx) * (1.f - wy), wx * (1.f - wy),
                       (1.f - wx) * wy,          wx * wy};
        int cx[4] = {x0, x0 + 1, x0,     x0 + 1};
        int cy[4] = {y0, y0,     y0 + 1, y0 + 1};

        float sk0 = 0.f, sk1 = 0.f, vv0 = 0.f, vv1 = 0.f;
        #pragma unroll
        for (int c = 0; c < 4; c++) {
            int ix = cx[c], iy = cy[c];
            if (ix >= 0 && ix < W && iy >= 0 && iy < H) {
                size_t rb = ((size_t)(b * NT + iy * W + ix)) * QKVW + head * HDIM;
                const __half2* kp = (const __half2*)(qkv + rb + CC);
                const __half2* vp = (const __half2*)(qkv + rb + 2 * CC);
                float2 kv = __half22float2(kp[lane]);
                float2 vv = __half22float2(vp[lane]);
                float w = cw[c];
                sk0 = fmaf(w, kv.x, sk0);
                sk1 = fmaf(w, kv.y, sk1);
                vv0 = fmaf(w, vv.x, vv0);
                vv1 = fmaf(w, vv.y, vv1);
            }
        }
        sv0[p] = vv0; sv1[p] = vv1;

        float dot = q.x * sk0 + q.y * sk1;
        #pragma unroll
        for (int o = 16; o > 0; o >>= 1)
            dot += __shfl_xor_sync(0xffffffffu, dot, o);
        dots[p] = dot * SCALE_ATTN;
    }

    float mx = fmaxf(fmaxf(dots[0], dots[1]), fmaxf(dots[2], dots[3]));
    float e[NPTS], es = 0.f;
    #pragma unroll
    for (int p = 0; p < NPTS; p++) { e[p] = __expf(dots[p] - mx); es += e[p]; }
    float inv = 1.0f / es;

    float out0 = 0.f, out1 = 0.f;
    #pragma unroll
    for (int p = 0; p < NPTS; p++) {
        float a = e[p] * inv;
        out0 = fmaf(a, sv0[p], out0);
        out1 = fmaf(a, sv1[p], out1);
    }
    __half2* o2p = (__half2*)(out + (size_t)bn * CC + head * HDIM);
    o2p[lane] = __floats2half2_rn(out0, out1);
}

// ---------------- launch ----------------------------------------------------
extern "C" void kernel_launch(void* const* d_in, const int* in_sizes, int n_in,
                              void* d_out, int out_size)
{
    const float* x      = (const float*)d_in[0];
    const float* refp   = (const float*)d_in[1];
    const float* n1w    = (const float*)d_in[2];
    const float* n1b    = (const float*)d_in[3];
    const float* qkv_w  = (const float*)d_in[4];
    const float* qkv_b  = (const float*)d_in[5];
    const float* off_w  = (const float*)d_in[6];
    const float* off_b  = (const float*)d_in[7];
    const float* proj_w = (const float*)d_in[8];
    const float* proj_b = (const float*)d_in[9];
    const float* n2w    = (const float*)d_in[10];
    const float* n2b    = (const float*)d_in[11];
    const float* fc1_w  = (const float*)d_in[12];
    const float* fc1_b  = (const float*)d_in[13];
    const float* fc2_w  = (const float*)d_in[14];
    const float* fc2_b  = (const float*)d_in[15];
    const int*   Hp     = (const int*)d_in[16];
    const int*   Wp     = (const int*)d_in[17];
    float* out = (float*)d_out;

    __half* h    = nullptr; cudaGetSymbolAddress((void**)&h,    g_h);
    __half* qkv  = nullptr; cudaGetSymbolAddress((void**)&qkv,  g_qkv);
    float*  offb = nullptr; cudaGetSymbolAddress((void**)&offb, g_off);
    __half* attn = nullptr; cudaGetSymbolAddress((void**)&attn, g_attn);
    __half* mlp  = nullptr; cudaGetSymbolAddress((void**)&mlp,  g_mlp);
    __half* wqkv = nullptr; cudaGetSymbolAddress((void**)&wqkv, g_wqkv);
    __half* wproj= nullptr; cudaGetSymbolAddress((void**)&wproj,g_wproj);
    __half* wfc1 = nullptr; cudaGetSymbolAddress((void**)&wfc1, g_wfc1);
    __half* wfc2 = nullptr; cudaGetSymbolAddress((void**)&wfc2, g_wfc2);
    __half* woff = nullptr; cudaGetSymbolAddress((void**)&woff, g_woff);
    float*  offbias = nullptr; cudaGetSymbolAddress((void**)&offbias, g_offb);

    static bool attr_done = false;
    if (!attr_done) {
        cudaFuncSetAttribute((const void*)hgemm_nt<0,__half>, cudaFuncAttributeMaxDynamicSharedMemorySize, HSM_BYTES);
        cudaFuncSetAttribute((const void*)hgemm_nt<0,float>,  cudaFuncAttributeMaxDynamicSharedMemorySize, HSM_BYTES);
        cudaFuncSetAttribute((const void*)hgemm_nt<1,__half>, cudaFuncAttributeMaxDynamicSharedMemorySize, HSM_BYTES);
        cudaFuncSetAttribute((const void*)hgemm_nt<2,float>,  cudaFuncAttributeMaxDynamicSharedMemorySize, HSM_BYTES);
        attr_done = true;
    }

    // 0) weight prep (fp32 -> fp16; tiny, deterministic)
    {
        int n;
        n = QKVW * CC / 4;      wconv_kernel<<<(n + 255) / 256, 256>>>(qkv_w,  wqkv,  n);
        n = CC * CC / 4;        wconv_kernel<<<(n + 255) / 256, 256>>>(proj_w, wproj, n);
        n = HIDDEN * CC / 4;    wconv_kernel<<<(n + 255) / 256, 256>>>(fc1_w,  wfc1,  n);
        n = CC * HIDDEN / 4;    wconv_kernel<<<(n + 255) / 256, 256>>>(fc2_w,  wfc2,  n);
        woffprep_kernel<<<(256 * CC + 255) / 256, 256>>>(off_w, off_b, woff, offbias);
    }

    // 1) ln1: x -> h (fp16)
    layernorm_kernel<<<MROWS, 256>>>(x, n1w, n1b, h);

    // 2) qkv = h @ qkv_w^T + b : [16384, 2304] fp16 out
    {
        dim3 grid(QKVW / 256, MROWS / 128);
        hgemm_nt<0,__half><<<grid, 256, HSM_BYTES>>>(h, CC, wqkv, qkv_b,
                                                     nullptr, 0, qkv, QKVW, CC, QKVW);
    }

    // 3) offsets = q @ off_w^T + off_b : [16384, 96] (fp16 GEMM, N padded 256)
    {
        dim3 grid(1, MROWS / 128);
        hgemm_nt<0,float><<<grid, 256, HSM_BYTES>>>(qkv, QKVW, woff, offbias,
                                                    nullptr, 0, offb, 96, CC, 96);
    }

    // 4) deformable sampling + attention -> attn [16384, 768] fp16
    {
        dim3 grid(BQ * NT, NHEADS / 4);
        attn_kernel<<<grid, 128>>>(qkv, offb, refp, attn, Hp, Wp);
    }

    // 5) x1 = x + attn @ proj_w^T + proj_b -> out (fp32)
    {
        dim3 grid(CC / 256, MROWS / 128);
        hgemm_nt<2,float><<<grid, 256, HSM_BYTES>>>(attn, CC, wproj, proj_b,
                                                    x, CC, out, CC, CC, CC);
    }

    // 6) ln2: out -> h (fp16)
    layernorm_kernel<<<MROWS, 256>>>(out, n2w, n2b, h);

    // 7) m = gelu(h @ fc1_w^T + fc1_b) -> mlp [16384, 3072] fp16
    {
        dim3 grid(HIDDEN / 256, MROWS / 128);
        hgemm_nt<1,__half><<<grid, 256, HSM_BYTES>>>(h, CC, wfc1, fc1_b,
                                                     nullptr, 0, mlp, HIDDEN, CC, HIDDEN);
    }

    // 8) out = out + mlp @ fc2_w^T + fc2_b (fp32)
    {
        dim3 grid(CC / 256, MROWS / 128);
        hgemm_nt<2,float><<<grid, 256, HSM_BYTES>>>(mlp, HIDDEN, wfc2, fc2_b,
                                                    out, CC, out, CC, HIDDEN, CC);
    }
}

// round 11
// speedup vs baseline: 1.4561x; 1.4561x over previous
#include <cuda_runtime.h>
#include <cuda_fp16.h>
#include <cstdint>
#include <math.h>

// Problem constants
#define BQ      4
#define NT      4096
#define CC      768
#define NHEADS  12
#define NPTS    4
#define HDIM    64
#define HIDDEN  3072
#define MROWS   (BQ*NT)          // 16384
#define SCALE_ATTN 0.125f        // 64^-0.5
#define QKVW    (3*CC)           // 2304

// ---------------- scratch (device globals; no cudaMalloc allowed) ----------
__device__ __half g_h[(size_t)MROWS * CC];          // ln out (fp16, GEMM A operand)
__device__ float  g_qkv[(size_t)MROWS * QKVW];      // qkv (fp32: attn + offsets GEMM)
__device__ float  g_off[(size_t)MROWS * NHEADS * NPTS * 2];
__device__ __half g_attn[(size_t)MROWS * CC];       // attention output (fp16)
__device__ __half g_mlp[(size_t)MROWS * HIDDEN];    // gelu(fc1) (fp16)
// fp16 weight copies (converted once per launch)
__device__ __half g_wqkv[(size_t)QKVW * CC];
__device__ __half g_wproj[(size_t)CC * CC];
__device__ __half g_wfc1[(size_t)HIDDEN * CC];
__device__ __half g_wfc2[(size_t)CC * HIDDEN];

// ---------------- weight conversion fp32 -> fp16 ---------------------------
__global__ __launch_bounds__(256) void wconv_kernel(
    const float* __restrict__ src, __half* __restrict__ dst, int n4)
{
    int i = blockIdx.x * 256 + threadIdx.x;
    if (i < n4) {
        float4 v = ((const float4*)src)[i];
        __half2 h0 = __floats2half2_rn(v.x, v.y);
        __half2 h1 = __floats2half2_rn(v.z, v.w);
        ((uint2*)dst)[i] = make_uint2(*(uint32_t*)&h0, *(uint32_t*)&h1);
    }
}

// ---------------- LayerNorm: fp32 in -> fp16 out ---------------------------
__global__ __launch_bounds__(256) void layernorm_kernel(
    const float* __restrict__ x, const float* __restrict__ w,
    const float* __restrict__ b, __half* __restrict__ out)
{
    int row = blockIdx.x;
    int t = threadIdx.x;
    const float* xr = x + (size_t)row * CC;
    float v0 = xr[t], v1 = xr[t + 256], v2 = xr[t + 512];
    float s  = v0 + v1 + v2;
    float sq = v0*v0 + v1*v1 + v2*v2;

    __shared__ float sh[16];
    #pragma unroll
    for (int o = 16; o > 0; o >>= 1) {
        s  += __shfl_xor_sync(0xffffffffu, s,  o);
        sq += __shfl_xor_sync(0xffffffffu, sq, o);
    }
    int wid = t >> 5, lane = t & 31;
    if (lane == 0) { sh[wid] = s; sh[8 + wid] = sq; }
    __syncthreads();
    if (t == 0) {
        float ts = 0.f, tq = 0.f;
        #pragma unroll
        for (int i = 0; i < 8; i++) { ts += sh[i]; tq += sh[8 + i]; }
        sh[0] = ts; sh[8] = tq;
    }
    __syncthreads();
    float mean = sh[0] * (1.0f / CC);
    float var  = sh[8] * (1.0f / CC) - mean * mean;
    float rstd = rsqrtf(var + 1e-5f);
    __half* orow = out + (size_t)row * CC;
    orow[t]       = __float2half_rn((v0 - mean) * rstd * w[t]       + b[t]);
    orow[t + 256] = __float2half_rn((v1 - mean) * rstd * w[t + 256] + b[t + 256]);
    orow[t + 512] = __float2half_rn((v2 - mean) * rstd * w[t + 512] + b[t + 512]);
}

// ============================================================================
// FP16 mma.sync GEMM: C[M,N] = A[M,K] * W[N,K]^T + bias (+epilogue)
// Block tile 128x256x32, warp tile 64x64, mma.m16n8k16, cp.async dbl-buffered,
// ldmatrix.x4 fragment loads. M%128==0, N%256==0, K%32==0, lda==K.
// EPI: 0 = bias, 1 = bias + exact GELU, 2 = bias + residual add
// ============================================================================
#define HSTR 40   // smem row stride in halves (32 + 8 pad) -> conflict-free LDSM
#define HS_A0 0        // 128*40 = 5120
#define HS_A1 5120
#define HS_B0 10240    // 256*40 = 10240
#define HS_B1 20480
#define HSM_BYTES ((20480 + 10240) * 2)   // 61440

__device__ __forceinline__ void cp_async16(void* smem_dst, const void* gmem_src) {
    uint32_t s = (uint32_t)__cvta_generic_to_shared(smem_dst);
    asm volatile("cp.async.cg.shared.global [%0], [%1], 16;\n" :: "r"(s), "l"(gmem_src));
}
__device__ __forceinline__ void ldsm_x4(uint32_t& r0, uint32_t& r1,
                                        uint32_t& r2, uint32_t& r3, uint32_t addr) {
    asm volatile("ldmatrix.sync.aligned.m8n8.x4.shared.b16 {%0,%1,%2,%3}, [%4];"
                 : "=r"(r0), "=r"(r1), "=r"(r2), "=r"(r3) : "r"(addr));
}

template<int EPI, typename OutT>
__global__ __launch_bounds__(256) void hgemm_nt(
    const __half* __restrict__ A,           // [M, K], lda == K
    const __half* __restrict__ Bw,          // [N, K], K contiguous
    const float* __restrict__ bias,
    const float* __restrict__ Res, int ldr,
    OutT* __restrict__ C, int ldc,
    int K)
{
    extern __shared__ __half smh[];
    const uint32_t sbase = (uint32_t)__cvta_generic_to_shared(smh);

    const int t = threadIdx.x;
    const int rowTile = blockIdx.y * 128;
    const int colTile = blockIdx.x * 256;

    const int warp = t >> 5, lane = t & 31;
    const int wm = (warp & 1) * 64;        // 2 warps along M
    const int wn = (warp >> 1) * 64;       // 4 warps along N
    const int g  = lane >> 2;              // 0..7
    const int t4 = lane & 3;               // 0..3

    // ldmatrix lane-address components
    const int lsub  = lane >> 3;           // 0..3 (8x8 sub-matrix id)
    const int lrow8 = lane & 7;            // row within 8x8

    float acc[4][8][4];
    #pragma unroll
    for (int i = 0; i < 4; i++)
        #pragma unroll
        for (int j = 0; j < 8; j++)
            #pragma unroll
            for (int r = 0; r < 4; r++) acc[i][j][r] = 0.f;

    const int NK = K / 32;
    const int Abase[2] = {HS_A0, HS_A1};
    const int Bbase[2] = {HS_B0, HS_B1};

    auto load_tile = [&](int kt, int buf) {
        const int kk = kt * 32;
        #pragma unroll
        for (int i = 0; i < 2; i++) {
            int c = t + i * 256;
            int row = c >> 2, kc = (c & 3) * 8;
            cp_async16(&smh[Abase[buf] + row * HSTR + kc],
                       A + (size_t)(rowTile + row) * K + kk + kc);
        }
        #pragma unroll
        for (int i = 0; i < 4; i++) {
            int c = t + i * 256;
            int row = c >> 2, kc = (c & 3) * 8;
            cp_async16(&smh[Bbase[buf] + row * HSTR + kc],
                       Bw + (size_t)(colTile + row) * K + kk + kc);
        }
        asm volatile("cp.async.commit_group;\n");
    };

    load_tile(0, 0);
    if (NK > 1) load_tile(1, 1);

    for (int kt = 0; kt < NK; kt++) {
        const int buf = kt & 1;
        if (kt + 1 < NK) asm volatile("cp.async.wait_group 1;\n");
        else             asm volatile("cp.async.wait_group 0;\n");
        __syncthreads();

        const uint32_t Asm = sbase + 2u * (uint32_t)Abase[buf];
        const uint32_t Bsm = sbase + 2u * (uint32_t)Bbase[buf];

        #pragma unroll
        for (int ks = 0; ks < 2; ks++) {
            const int k0 = ks * 16;
            // A fragments: 4 m16k16 tiles, one ldmatrix.x4 each.
            // sub0:(r,k) sub1:(r+8,k) sub2:(r,k+8) sub3:(r+8,k+8)
            uint32_t afr[4][4];
            #pragma unroll
            for (int i = 0; i < 4; i++) {
                int row = wm + i * 16 + ((lsub & 1) << 3) + lrow8;
                int col = k0 + ((lsub >> 1) << 3);
                ldsm_x4(afr[i][0], afr[i][1], afr[i][2], afr[i][3],
                        Asm + 2u * (uint32_t)(row * HSTR + col));
            }
            // B fragments: 8 n8k16 tiles, one ldmatrix.x4 per pair.
            // sub0:(j,k) sub1:(j,k+8) sub2:(j+1,k) sub3:(j+1,k+8)
            uint32_t bfr[8][2];
            #pragma unroll
            for (int jp = 0; jp < 4; jp++) {
                int row = wn + (jp * 2 + (lsub >> 1)) * 8 + lrow8;
                int col = k0 + ((lsub & 1) << 3);
                ldsm_x4(bfr[2*jp][0], bfr[2*jp][1], bfr[2*jp+1][0], bfr[2*jp+1][1],
                        Bsm + 2u * (uint32_t)(row * HSTR + col));
            }
            #pragma unroll
            for (int i = 0; i < 4; i++)
                #pragma unroll
                for (int j = 0; j < 8; j++) {
                    asm volatile(
                        "mma.sync.aligned.m16n8k16.row.col.f32.f16.f16.f32 "
                        "{%0,%1,%2,%3}, {%4,%5,%6,%7}, {%8,%9}, {%0,%1,%2,%3};\n"
                        : "+f"(acc[i][j][0]), "+f"(acc[i][j][1]),
                          "+f"(acc[i][j][2]), "+f"(acc[i][j][3])
                        : "r"(afr[i][0]), "r"(afr[i][1]), "r"(afr[i][2]), "r"(afr[i][3]),
                          "r"(bfr[j][0]), "r"(bfr[j][1]));
                }
        }
        __syncthreads();

        if (kt + 2 < NK) load_tile(kt + 2, buf);
    }

    // epilogue: acc[i][j] -> rows {wm+i*16+g, +8}, cols {wn+j*8+2*t4, +1}
    #pragma unroll
    for (int i = 0; i < 4; i++) {
        #pragma unroll
        for (int half = 0; half < 2; half++) {
            int r = rowTile + wm + i * 16 + g + half * 8;
            OutT* crow = C + (size_t)r * ldc;
            const float* rrow = (EPI == 2) ? (Res + (size_t)r * ldr) : nullptr;
            #pragma unroll
            for (int j = 0; j < 8; j++) {
                int cg = colTile + wn + j * 8 + t4 * 2;
                float v0 = acc[i][j][half * 2 + 0] + bias[cg];
                float v1 = acc[i][j][half * 2 + 1] + bias[cg + 1];
                if (EPI == 1) {
                    v0 = 0.5f * v0 * (1.0f + erff(v0 * 0.70710678118654752f));
                    v1 = 0.5f * v1 * (1.0f + erff(v1 * 0.70710678118654752f));
                }
                if (EPI == 2) { v0 += rrow[cg]; v1 += rrow[cg + 1]; }
                if (sizeof(OutT) == 2) {
                    __half2 hv = __floats2half2_rn(v0, v1);
                    *(__half2*)((__half*)crow + cg) = hv;
                } else {
                    *(float2*)((float*)crow + cg) = make_float2(v0, v1);
                }
            }
        }
    }
}

// ---------------- fp32 SGEMM (small N=96 offsets GEMM) ---------------------
__global__ __launch_bounds__(256) void sgemm_nt(
    const float* __restrict__ A, int lda,
    const float* __restrict__ Bw,
    const float* __restrict__ bias,
    float* __restrict__ C, int ldc,
    int M, int N, int K)
{
    __shared__ float As[8][128];
    __shared__ float Bs[8][128];

    int t = threadIdx.x;
    int rowTile = blockIdx.y * 128;
    int colTile = blockIdx.x * 128;

    int ldRow = t >> 1;
    int ldCol = (t & 1) * 4;

    const float* Aptr = A + (size_t)(rowTile + ldRow) * lda + ldCol;
    bool bValid = (colTile + ldRow) < N;
    const float* Bptr = Bw + (size_t)(colTile + ldRow) * K + ldCol;

    int ty = t >> 4, tx = t & 15;
    float acc[8][8];
    #pragma unroll
    for (int i = 0; i < 8; i++)
        #pragma unroll
        for (int j = 0; j < 8; j++) acc[i][j] = 0.f;

    for (int k0 = 0; k0 < K; k0 += 8) {
        float4 av = *(const float4*)(Aptr + k0);
        float4 bv = bValid ? *(const float4*)(Bptr + k0)
                           : make_float4(0.f, 0.f, 0.f, 0.f);
        As[ldCol + 0][ldRow] = av.x; As[ldCol + 1][ldRow] = av.y;
        As[ldCol + 2][ldRow] = av.z; As[ldCol + 3][ldRow] = av.w;
        Bs[ldCol + 0][ldRow] = bv.x; Bs[ldCol + 1][ldRow] = bv.y;
        Bs[ldCol + 2][ldRow] = bv.z; Bs[ldCol + 3][ldRow] = bv.w;
        __syncthreads();

        #pragma unroll
        for (int k = 0; k < 8; k++) {
            float4 a0 = *(const float4*)&As[k][ty * 8];
            float4 a1 = *(const float4*)&As[k][ty * 8 + 4];
            float4 b0 = *(const float4*)&Bs[k][tx * 8];
            float4 b1 = *(const float4*)&Bs[k][tx * 8 + 4];
            float ar[8] = {a0.x, a0.y, a0.z, a0.w, a1.x, a1.y, a1.z, a1.w};
            float br[8] = {b0.x, b0.y, b0.z, b0.w, b1.x, b1.y, b1.z, b1.w};
            #pragma unroll
            for (int i = 0; i < 8; i++)
                #pragma unroll
                for (int j = 0; j < 8; j++)
                    acc[i][j] = fmaf(ar[i], br[j], acc[i][j]);
        }
        __syncthreads();
    }

    #pragma unroll
    for (int i = 0; i < 8; i++) {
        int r = rowTile + ty * 8 + i;
        float* crow = C + (size_t)r * ldc;
        #pragma unroll
        for (int j = 0; j < 8; j++) {
            int c = colTile + tx * 8 + j;
            if (c < N) crow[c] = acc[i][j] + bias[c];
        }
    }
}

// ---------------- deformable sampling + attention (4 heads / 128-thr block)-
__global__ __launch_bounds__(128) void attn_kernel(
    const float* __restrict__ qkv,    // [M, 2304] fp32
    const float* __restrict__ off,    // [M, 96]
    const float* __restrict__ refp,   // [M, 2]
    __half* __restrict__ out,         // [M, 768] fp16
    const int* __restrict__ Hp, const int* __restrict__ Wp)
{
    int bn   = blockIdx.x;
    int head = blockIdx.y * 4 + (threadIdx.x >> 5);
    int lane = threadIdx.x & 31;
    int b = bn / NT;

    int H = *Hp, W = *Wp;
    float fW = (float)W, fH = (float)H;

    size_t qbase = (size_t)bn * QKVW + head * HDIM;
    float q0 = qkv[qbase + lane];
    float q1 = qkv[qbase + lane + 32];

    float ref0 = refp[(size_t)bn * 2 + 0];
    float ref1 = refp[(size_t)bn * 2 + 1];

    const float* offp = off + (size_t)bn * (NHEADS * NPTS * 2) + head * (NPTS * 2);

    float dots[NPTS];
    float sv0[NPTS], sv1[NPTS];

    #pragma unroll
    for (int p = 0; p < NPTS; p++) {
        float o0 = offp[p * 2 + 0];
        float o1 = offp[p * 2 + 1];
        float gx = 2.0f * (ref0 + o0 / fW) - 1.0f;
        float gy = 2.0f * (ref1 + o1 / fH) - 1.0f;
        float x = ((gx + 1.0f) * fW - 1.0f) * 0.5f;
        float y = ((gy + 1.0f) * fH - 1.0f) * 0.5f;
        float x0f = floorf(x), y0f = floorf(y);
        float wx = x - x0f, wy = y - y0f;
        int x0 = (int)x0f, y0 = (int)y0f;

        float cw[4] = {(1.f - wx) * (1.f - wy), wx * (1.f - wy),
                       (1.f - wx) * wy,          wx * wy};
        int cx[4] = {x0, x0 + 1, x0,     x0 + 1};
        int cy[4] = {y0, y0,     y0 + 1, y0 + 1};

        float sk0 = 0.f, sk1 = 0.f, vv0 = 0.f, vv1 = 0.f;
        #pragma unroll
        for (int c = 0; c < 4; c++) {
            int ix = cx[c], iy = cy[c];
            if (ix >= 0 && ix < W && iy >= 0 && iy < H) {
                size_t rb = ((size_t)(b * NT + iy * W + ix)) * QKVW + head * HDIM;
                const float* kp = qkv + rb + CC;
                const float* vp = qkv + rb + 2 * CC;
                float w = cw[c];
                sk0 = fmaf(w, kp[lane],      sk0);
                sk1 = fmaf(w, kp[lane + 32], sk1);
                vv0 = fmaf(w, vp[lane],      vv0);
                vv1 = fmaf(w, vp[lane + 32], vv1);
            }
        }
        sv0[p] = vv0; sv1[p] = vv1;

        float dot = q0 * sk0 + q1 * sk1;
        #pragma unroll
        for (int o = 16; o > 0; o >>= 1)
            dot += __shfl_xor_sync(0xffffffffu, dot, o);
        dots[p] = dot * SCALE_ATTN;
    }

    float mx = fmaxf(fmaxf(dots[0], dots[1]), fmaxf(dots[2], dots[3]));
    float e[NPTS], es = 0.f;
    #pragma unroll
    for (int p = 0; p < NPTS; p++) { e[p] = __expf(dots[p] - mx); es += e[p]; }
    float inv = 1.0f / es;

    float out0 = 0.f, out1 = 0.f;
    #pragma unroll
    for (int p = 0; p < NPTS; p++) {
        float a = e[p] * inv;
        out0 = fmaf(a, sv0[p], out0);
        out1 = fmaf(a, sv1[p], out1);
    }
    size_t ob = (size_t)bn * CC + head * HDIM;
    out[ob + lane]      = __float2half_rn(out0);
    out[ob + lane + 32] = __float2half_rn(out1);
}

// ---------------- launch ----------------------------------------------------
extern "C" void kernel_launch(void* const* d_in, const int* in_sizes, int n_in,
                              void* d_out, int out_size)
{
    const float* x      = (const float*)d_in[0];
    const float* refp   = (const float*)d_in[1];
    const float* n1w    = (const float*)d_in[2];
    const float* n1b    = (const float*)d_in[3];
    const float* qkv_w  = (const float*)d_in[4];
    const float* qkv_b  = (const float*)d_in[5];
    const float* off_w  = (const float*)d_in[6];
    const float* off_b  = (const float*)d_in[7];
    const float* proj_w = (const float*)d_in[8];
    const float* proj_b = (const float*)d_in[9];
    const float* n2w    = (const float*)d_in[10];
    const float* n2b    = (const float*)d_in[11];
    const float* fc1_w  = (const float*)d_in[12];
    const float* fc1_b  = (const float*)d_in[13];
    const float* fc2_w  = (const float*)d_in[14];
    const float* fc2_b  = (const float*)d_in[15];
    const int*   Hp     = (const int*)d_in[16];
    const int*   Wp     = (const int*)d_in[17];
    float* out = (float*)d_out;

    __half* h    = nullptr; cudaGetSymbolAddress((void**)&h,    g_h);
    float*  qkv  = nullptr; cudaGetSymbolAddress((void**)&qkv,  g_qkv);
    float*  offb = nullptr; cudaGetSymbolAddress((void**)&offb, g_off);
    __half* attn = nullptr; cudaGetSymbolAddress((void**)&attn, g_attn);
    __half* mlp  = nullptr; cudaGetSymbolAddress((void**)&mlp,  g_mlp);
    __half* wqkv = nullptr; cudaGetSymbolAddress((void**)&wqkv, g_wqkv);
    __half* wproj= nullptr; cudaGetSymbolAddress((void**)&wproj,g_wproj);
    __half* wfc1 = nullptr; cudaGetSymbolAddress((void**)&wfc1, g_wfc1);
    __half* wfc2 = nullptr; cudaGetSymbolAddress((void**)&wfc2, g_wfc2);

    static bool attr_done = false;
    if (!attr_done) {
        cudaFuncSetAttribute((const void*)hgemm_nt<0,float>,  cudaFuncAttributeMaxDynamicSharedMemorySize, HSM_BYTES);
        cudaFuncSetAttribute((const void*)hgemm_nt<1,__half>, cudaFuncAttributeMaxDynamicSharedMemorySize, HSM_BYTES);
        cudaFuncSetAttribute((const void*)hgemm_nt<2,float>,  cudaFuncAttributeMaxDynamicSharedMemorySize, HSM_BYTES);
        attr_done = true;
    }

    // 0) convert weights to fp16 (tiny; same every call -> deterministic)
    {
        int n;
        n = QKVW * CC / 4;      wconv_kernel<<<(n + 255) / 256, 256>>>(qkv_w,  wqkv,  n);
        n = CC * CC / 4;        wconv_kernel<<<(n + 255) / 256, 256>>>(proj_w, wproj, n);
        n = HIDDEN * CC / 4;    wconv_kernel<<<(n + 255) / 256, 256>>>(fc1_w,  wfc1,  n);
        n = CC * HIDDEN / 4;    wconv_kernel<<<(n + 255) / 256, 256>>>(fc2_w,  wfc2,  n);
    }

    // 1) ln1: x -> h (fp16)
    layernorm_kernel<<<MROWS, 256>>>(x, n1w, n1b, h);

    // 2) qkv = h @ qkv_w^T + b : [16384, 2304] fp32 out
    {
        dim3 grid(QKVW / 256, MROWS / 128);
        hgemm_nt<0,float><<<grid, 256, HSM_BYTES>>>(h, wqkv, qkv_b,
                                                    nullptr, 0, qkv, QKVW, CC);
    }

    // 3) offsets = q @ off_w^T + off_b : [16384, 96]  (small; fp32 path)
    {
        dim3 grid(1, MROWS / 128);
        sgemm_nt<<<grid, 256>>>(qkv, QKVW, off_w, off_b,
                                offb, NHEADS * NPTS * 2,
                                MROWS, NHEADS * NPTS * 2, CC);
    }

    // 4) deformable sampling + attention -> attn [16384, 768] fp16
    {
        dim3 grid(BQ * NT, NHEADS / 4);
        attn_kernel<<<grid, 128>>>(qkv, offb, refp, attn, Hp, Wp);
    }

    // 5) x1 = x + attn @ proj_w^T + proj_b -> out (fp32)
    {
        dim3 grid(CC / 256, MROWS / 128);
        hgemm_nt<2,float><<<grid, 256, HSM_BYTES>>>(attn, wproj, proj_b,
                                                    x, CC, out, CC, CC);
    }

    // 6) ln2: out -> h (fp16)
    layernorm_kernel<<<MROWS, 256>>>(out, n2w, n2b, h);

    // 7) m = gelu(h @ fc1_w^T + fc1_b) -> mlp [16384, 3072] fp16
    {
        dim3 grid(HIDDEN / 256, MROWS / 128);
        hgemm_nt<1,__half><<<grid, 256, HSM_BYTES>>>(h, wfc1, fc1_b,
                                                     nullptr, 0, mlp, HIDDEN, CC);
    }

    // 8) out = out + mlp @ fc2_w^T + fc2_b (fp32)
    {
        dim3 grid(CC / 256, MROWS / 128);
        hgemm_nt<2,float><<<grid, 256, HSM_BYTES>>>(mlp, wfc2, fc2_b,
                                                    out, CC, out, CC, HIDDEN);
    }
}

// round 12
// speedup vs baseline: 1.5567x; 1.0691x over previous
#include <cuda_runtime.h>
#include <cuda_fp16.h>
#include <cstdint>
#include <math.h>

// Problem constants
#define BQ      4
#define NT      4096
#define CC      768
#define NHEADS  12
#define NPTS    4
#define HDIM    64
#define HIDDEN  3072
#define MROWS   (BQ*NT)          // 16384
#define SCALE_ATTN 0.125f        // 64^-0.5
#define QKVW    (3*CC)           // 2304
#define QX      2560             // qkv + 96 offset cols, padded to 256
#define NOFF    96

// ---------------- scratch (device globals; no cudaMalloc allowed) ----------
__device__ __half g_h[(size_t)MROWS * CC];          // ln out (fp16 GEMM A)
__device__ float  g_qkvx[(size_t)MROWS * QX];       // qkv + offsets fused (fp32)
__device__ __half g_attn[(size_t)MROWS * CC];       // attention output (fp16)
__device__ __half g_mlp[(size_t)MROWS * HIDDEN];    // gelu(fc1) (fp16)
// fp16 weight copies (prepared once per launch)
__device__ __half g_wqkvx[(size_t)QX * CC];         // qkv_w ++ Weff ++ zero pad
__device__ float  g_biasx[QX];                      // qkv_b ++ beff ++ 0
__device__ __half g_wproj[(size_t)CC * CC];
__device__ __half g_wfc1[(size_t)HIDDEN * CC];
__device__ __half g_wfc2[(size_t)CC * HIDDEN];

// ---------------- weight prep ----------------------------------------------
__global__ __launch_bounds__(256) void wconv_kernel(
    const float* __restrict__ src, __half* __restrict__ dst, int n4)
{
    int i = blockIdx.x * 256 + threadIdx.x;
    if (i < n4) {
        float4 v = ((const float4*)src)[i];
        __half2 h0 = __floats2half2_rn(v.x, v.y);
        __half2 h1 = __floats2half2_rn(v.z, v.w);
        ((uint2*)dst)[i] = make_uint2(*(uint32_t*)&h0, *(uint32_t*)&h1);
    }
}

// Weff[n][j] = sum_k off_w[n][k] * qkv_w[k][j]  (q rows of qkv_w), n<96
// grid (96, 3), block 256
__global__ __launch_bounds__(256) void wcompose_kernel(
    const float* __restrict__ qkv_w, const float* __restrict__ off_w,
    __half* __restrict__ wqkvx)
{
    int n = blockIdx.x;
    int j = blockIdx.y * 256 + threadIdx.x;
    float s = 0.f;
    for (int k = 0; k < CC; k++)
        s = fmaf(__ldg(&off_w[n * CC + k]), qkv_w[(size_t)k * CC + j], s);
    wqkvx[(size_t)(QKVW + n) * CC + j] = __float2half_rn(s);
}

// bias vector [QX] and zero-pad rows 2400..2559 of wqkvx
__global__ __launch_bounds__(256) void biasprep_kernel(
    const float* __restrict__ qkv_b, const float* __restrict__ off_w,
    const float* __restrict__ off_b, float* __restrict__ biasx,
    __half* __restrict__ wqkvx)
{
    int i = blockIdx.x * 256 + threadIdx.x;
    if (i < QX) {
        if (i < QKVW) biasx[i] = qkv_b[i];
        else if (i < QKVW + NOFF) {
            int n = i - QKVW;
            float s = off_b[n];
            for (int k = 0; k < CC; k++) s = fmaf(off_w[n * CC + k], qkv_b[k], s);
            biasx[i] = s;
        } else biasx[i] = 0.f;
    }
    // zero pad rows (160*768 = 122880 halves)
    for (int z = blockIdx.x * 256 + threadIdx.x; z < (QX - QKVW - NOFF) * CC;
         z += gridDim.x * 256)
        wqkvx[(size_t)(QKVW + NOFF) * CC + z] = __float2half_rn(0.f);
}

// ---------------- LayerNorm: fp32 in -> fp16 out ---------------------------
__global__ __launch_bounds__(256) void layernorm_kernel(
    const float* __restrict__ x, const float* __restrict__ w,
    const float* __restrict__ b, __half* __restrict__ out)
{
    int row = blockIdx.x;
    int t = threadIdx.x;
    const float* xr = x + (size_t)row * CC;
    float v0 = xr[t], v1 = xr[t + 256], v2 = xr[t + 512];
    float s  = v0 + v1 + v2;
    float sq = v0*v0 + v1*v1 + v2*v2;

    __shared__ float sh[16];
    #pragma unroll
    for (int o = 16; o > 0; o >>= 1) {
        s  += __shfl_xor_sync(0xffffffffu, s,  o);
        sq += __shfl_xor_sync(0xffffffffu, sq, o);
    }
    int wid = t >> 5, lane = t & 31;
    if (lane == 0) { sh[wid] = s; sh[8 + wid] = sq; }
    __syncthreads();
    if (t == 0) {
        float ts = 0.f, tq = 0.f;
        #pragma unroll
        for (int i = 0; i < 8; i++) { ts += sh[i]; tq += sh[8 + i]; }
        sh[0] = ts; sh[8] = tq;
    }
    __syncthreads();
    float mean = sh[0] * (1.0f / CC);
    float var  = sh[8] * (1.0f / CC) - mean * mean;
    float rstd = rsqrtf(var + 1e-5f);
    __half* orow = out + (size_t)row * CC;
    orow[t]       = __float2half_rn((v0 - mean) * rstd * w[t]       + b[t]);
    orow[t + 256] = __float2half_rn((v1 - mean) * rstd * w[t + 256] + b[t + 256]);
    orow[t + 512] = __float2half_rn((v2 - mean) * rstd * w[t + 512] + b[t + 512]);
}

// ============================================================================
// FP16 mma.sync GEMM: C[M,N] = A[M,K] * W[N,K]^T + bias (+epilogue)
// Block tile 128x256x32, warp tile 64x64, mma.m16n8k16, 3-stage cp.async.
// M%128==0, K%32==0, lda==K; col stores guarded by nvalid (even).
// EPI: 0 = bias, 1 = bias + exact GELU, 2 = bias + residual add
// ============================================================================
#define HSTR 40        // smem row stride in halves (32 + 8 pad)
#define STG_H 15360    // halves per stage: A 128*40 + B 256*40
#define HSM_BYTES (3 * STG_H * 2)   // 92160

__device__ __forceinline__ void cp_async16(void* smem_dst, const void* gmem_src) {
    uint32_t s = (uint32_t)__cvta_generic_to_shared(smem_dst);
    asm volatile("cp.async.cg.shared.global [%0], [%1], 16;\n" :: "r"(s), "l"(gmem_src));
}

template<int EPI, typename OutT>
__global__ __launch_bounds__(256) void hgemm_nt(
    const __half* __restrict__ A,           // [M, K], lda == K
    const __half* __restrict__ Bw,          // [N', K], K contiguous
    const float* __restrict__ bias,
    const float* __restrict__ Res, int ldr,
    OutT* __restrict__ C, int ldc,
    int K, int nvalid)
{
    extern __shared__ __half smh[];

    const int t = threadIdx.x;
    const int rowTile = blockIdx.y * 128;
    const int colTile = blockIdx.x * 256;

    const int warp = t >> 5, lane = t & 31;
    const int wm = (warp & 1) * 64;        // 2 warps along M
    const int wn = (warp >> 1) * 64;       // 4 warps along N
    const int g  = lane >> 2;              // 0..7
    const int t4 = lane & 3;               // 0..3

    float acc[4][8][4];
    #pragma unroll
    for (int i = 0; i < 4; i++)
        #pragma unroll
        for (int j = 0; j < 8; j++)
            #pragma unroll
            for (int r = 0; r < 4; r++) acc[i][j][r] = 0.f;

    const int NK = K / 32;

    auto load_tile = [&](int kt, int buf) {
        const int kk = kt * 32;
        __half* As = smh + buf * STG_H;
        __half* Bs = As + 128 * HSTR;
        #pragma unroll
        for (int i = 0; i < 2; i++) {
            int c = t + i * 256;
            int row = c >> 2, kc = (c & 3) * 8;
            cp_async16(&As[row * HSTR + kc],
                       A + (size_t)(rowTile + row) * K + kk + kc);
        }
        #pragma unroll
        for (int i = 0; i < 4; i++) {
            int c = t + i * 256;
            int row = c >> 2, kc = (c & 3) * 8;
            cp_async16(&Bs[row * HSTR + kc],
                       Bw + (size_t)(colTile + row) * K + kk + kc);
        }
        asm volatile("cp.async.commit_group;\n");
    };

    load_tile(0, 0);
    if (NK > 1) load_tile(1, 1);

    for (int kt = 0; kt < NK; kt++) {
        const int buf = kt % 3;
        if (kt + 1 < NK) asm volatile("cp.async.wait_group 1;\n");
        else             asm volatile("cp.async.wait_group 0;\n");
        __syncthreads();

        const __half* As = smh + buf * STG_H;
        const __half* Bs = As + 128 * HSTR;

        #pragma unroll
        for (int ks = 0; ks < 2; ks++) {
            const int k0 = ks * 16;
            uint32_t afr[4][4];
            #pragma unroll
            for (int i = 0; i < 4; i++) {
                int rr = wm + i * 16 + g;
                afr[i][0] = *(const uint32_t*)&As[(rr    ) * HSTR + k0 + 2 * t4];
                afr[i][1] = *(const uint32_t*)&As[(rr + 8) * HSTR + k0 + 2 * t4];
                afr[i][2] = *(const uint32_t*)&As[(rr    ) * HSTR + k0 + 2 * t4 + 8];
                afr[i][3] = *(const uint32_t*)&As[(rr + 8) * HSTR + k0 + 2 * t4 + 8];
            }
            uint32_t bfr[8][2];
            #pragma unroll
            for (int j = 0; j < 8; j++) {
                int cc = wn + j * 8 + g;
                bfr[j][0] = *(const uint32_t*)&Bs[cc * HSTR + k0 + 2 * t4];
                bfr[j][1] = *(const uint32_t*)&Bs[cc * HSTR + k0 + 2 * t4 + 8];
            }
            #pragma unroll
            for (int i = 0; i < 4; i++)
                #pragma unroll
                for (int j = 0; j < 8; j++) {
                    asm volatile(
                        "mma.sync.aligned.m16n8k16.row.col.f32.f16.f16.f32 "
                        "{%0,%1,%2,%3}, {%4,%5,%6,%7}, {%8,%9}, {%0,%1,%2,%3};\n"
                        : "+f"(acc[i][j][0]), "+f"(acc[i][j][1]),
                          "+f"(acc[i][j][2]), "+f"(acc[i][j][3])
                        : "r"(afr[i][0]), "r"(afr[i][1]), "r"(afr[i][2]), "r"(afr[i][3]),
                          "r"(bfr[j][0]), "r"(bfr[j][1]));
                }
        }

        if (kt + 2 < NK) load_tile(kt + 2, (kt + 2) % 3);
    }

    // epilogue
    #pragma unroll
    for (int i = 0; i < 4; i++) {
        #pragma unroll
        for (int half = 0; half < 2; half++) {
            int r = rowTile + wm + i * 16 + g + half * 8;
            OutT* crow = C + (size_t)r * ldc;
            const float* rrow = (EPI == 2) ? (Res + (size_t)r * ldr) : nullptr;
            #pragma unroll
            for (int j = 0; j < 8; j++) {
                int cg = colTile + wn + j * 8 + t4 * 2;
                if (cg >= nvalid) continue;
                float v0 = acc[i][j][half * 2 + 0] + bias[cg];
                float v1 = acc[i][j][half * 2 + 1] + bias[cg + 1];
                if (EPI == 1) {
                    v0 = 0.5f * v0 * (1.0f + erff(v0 * 0.70710678118654752f));
                    v1 = 0.5f * v1 * (1.0f + erff(v1 * 0.70710678118654752f));
                }
                if (EPI == 2) { v0 += rrow[cg]; v1 += rrow[cg + 1]; }
                if (sizeof(OutT) == 2) {
                    __half2 hv = __floats2half2_rn(v0, v1);
                    *(__half2*)((__half*)crow + cg) = hv;
                } else {
                    *(float2*)((float*)crow + cg) = make_float2(v0, v1);
                }
            }
        }
    }
}

// ---------------- deformable sampling + attention --------------------------
// 4 heads / 128-thr block; lane owns channels {2*lane, 2*lane+1}
__global__ __launch_bounds__(128) void attn_kernel(
    const float* __restrict__ qkvx,   // [M, 2560] fp32 (qkv ++ offsets)
    const float* __restrict__ refp,   // [M, 2]
    __half* __restrict__ out,         // [M, 768] fp16
    const int* __restrict__ Hp, const int* __restrict__ Wp)
{
    int bn   = blockIdx.x;
    int head = blockIdx.y * 4 + (threadIdx.x >> 5);
    int lane = threadIdx.x & 31;
    int b = bn / NT;

    int H = *Hp, W = *Wp;
    float fW = (float)W, fH = (float)H;

    const float* rowq = qkvx + (size_t)bn * QX;
    float2 q = ((const float2*)(rowq + head * HDIM))[lane];

    float ref0 = refp[(size_t)bn * 2 + 0];
    float ref1 = refp[(size_t)bn * 2 + 1];

    const float* offp = rowq + QKVW + head * (NPTS * 2);

    float dots[NPTS];
    float sv0[NPTS], sv1[NPTS];

    #pragma unroll
    for (int p = 0; p < NPTS; p++) {
        float o0 = offp[p * 2 + 0];
        float o1 = offp[p * 2 + 1];
        float gx = 2.0f * (ref0 + o0 / fW) - 1.0f;
        float gy = 2.0f * (ref1 + o1 / fH) - 1.0f;
        float x = ((gx + 1.0f) * fW - 1.0f) * 0.5f;
        float y = ((gy + 1.0f) * fH - 1.0f) * 0.5f;
        float x0f = floorf(x), y0f = floorf(y);
        float wx = x - x0f, wy = y - y0f;
        int x0 = (int)x0f, y0 = (int)y0f;

        float cw[4] = {(1.f - wx) * (1.f - wy), wx * (1.f - wy),
                       (1.f - wx) * wy,          wx * wy};
        int cx[4] = {x0, x0 + 1, x0,     x0 + 1};
        int cy[4] = {y0, y0,     y0 + 1, y0 + 1};

        float sk0 = 0.f, sk1 = 0.f, vv0 = 0.f, vv1 = 0.f;
        #pragma unroll
        for (int c = 0; c < 4; c++) {
            int ix = cx[c], iy = cy[c];
            if (ix >= 0 && ix < W && iy >= 0 && iy < H) {
                const float* rowk = qkvx + (size_t)(b * NT + iy * W + ix) * QX
                                  + head * HDIM;
                float2 kv = ((const float2*)(rowk + CC))[lane];
                float2 vv = ((const float2*)(rowk + 2 * CC))[lane];
                float w = cw[c];
                sk0 = fmaf(w, kv.x, sk0);
                sk1 = fmaf(w, kv.y, sk1);
                vv0 = fmaf(w, vv.x, vv0);
                vv1 = fmaf(w, vv.y, vv1);
            }
        }
        sv0[p] = vv0; sv1[p] = vv1;

        float dot = q.x * sk0 + q.y * sk1;
        #pragma unroll
        for (int o = 16; o > 0; o >>= 1)
            dot += __shfl_xor_sync(0xffffffffu, dot, o);
        dots[p] = dot * SCALE_ATTN;
    }

    float mx = fmaxf(fmaxf(dots[0], dots[1]), fmaxf(dots[2], dots[3]));
    float e[NPTS], es = 0.f;
    #pragma unroll
    for (int p = 0; p < NPTS; p++) { e[p] = __expf(dots[p] - mx); es += e[p]; }
    float inv = 1.0f / es;

    float out0 = 0.f, out1 = 0.f;
    #pragma unroll
    for (int p = 0; p < NPTS; p++) {
        float a = e[p] * inv;
        out0 = fmaf(a, sv0[p], out0);
        out1 = fmaf(a, sv1[p], out1);
    }
    __half2* o2 = (__half2*)(out + (size_t)bn * CC + head * HDIM);
    o2[lane] = __floats2half2_rn(out0, out1);
}

// ---------------- launch ----------------------------------------------------
extern "C" void kernel_launch(void* const* d_in, const int* in_sizes, int n_in,
                              void* d_out, int out_size)
{
    const float* x      = (const float*)d_in[0];
    const float* refp   = (const float*)d_in[1];
    const float* n1w    = (const float*)d_in[2];
    const float* n1b    = (const float*)d_in[3];
    const float* qkv_w  = (const float*)d_in[4];
    const float* qkv_b  = (const float*)d_in[5];
    const float* off_w  = (const float*)d_in[6];
    const float* off_b  = (const float*)d_in[7];
    const float* proj_w = (const float*)d_in[8];
    const float* proj_b = (const float*)d_in[9];
    const float* n2w    = (const float*)d_in[10];
    const float* n2b    = (const float*)d_in[11];
    const float* fc1_w  = (const float*)d_in[12];
    const float* fc1_b  = (const float*)d_in[13];
    const float* fc2_w  = (const float*)d_in[14];
    const float* fc2_b  = (const float*)d_in[15];
    const int*   Hp     = (const int*)d_in[16];
    const int*   Wp     = (const int*)d_in[17];
    float* out = (float*)d_out;

    __half* h     = nullptr; cudaGetSymbolAddress((void**)&h,     g_h);
    float*  qkvx  = nullptr; cudaGetSymbolAddress((void**)&qkvx,  g_qkvx);
    __half* attn  = nullptr; cudaGetSymbolAddress((void**)&attn,  g_attn);
    __half* mlp   = nullptr; cudaGetSymbolAddress((void**)&mlp,   g_mlp);
    __half* wqkvx = nullptr; cudaGetSymbolAddress((void**)&wqkvx, g_wqkvx);
    float*  biasx = nullptr; cudaGetSymbolAddress((void**)&biasx, g_biasx);
    __half* wproj = nullptr; cudaGetSymbolAddress((void**)&wproj, g_wproj);
    __half* wfc1  = nullptr; cudaGetSymbolAddress((void**)&wfc1,  g_wfc1);
    __half* wfc2  = nullptr; cudaGetSymbolAddress((void**)&wfc2,  g_wfc2);

    static bool attr_done = false;
    if (!attr_done) {
        cudaFuncSetAttribute((const void*)hgemm_nt<0,float>,  cudaFuncAttributeMaxDynamicSharedMemorySize, HSM_BYTES);
        cudaFuncSetAttribute((const void*)hgemm_nt<1,__half>, cudaFuncAttributeMaxDynamicSharedMemorySize, HSM_BYTES);
        cudaFuncSetAttribute((const void*)hgemm_nt<2,float>,  cudaFuncAttributeMaxDynamicSharedMemorySize, HSM_BYTES);
        attr_done = true;
    }

    // 0) weight prep
    {
        int n;
        n = QKVW * CC / 4;      wconv_kernel<<<(n + 255) / 256, 256>>>(qkv_w,  wqkvx, n);
        n = CC * CC / 4;        wconv_kernel<<<(n + 255) / 256, 256>>>(proj_w, wproj, n);
        n = HIDDEN * CC / 4;    wconv_kernel<<<(n + 255) / 256, 256>>>(fc1_w,  wfc1,  n);
        n = CC * HIDDEN / 4;    wconv_kernel<<<(n + 255) / 256, 256>>>(fc2_w,  wfc2,  n);
        { dim3 g(NOFF, CC / 256); wcompose_kernel<<<g, 256>>>(qkv_w, off_w, wqkvx); }
        biasprep_kernel<<<(QX + 255) / 256, 256>>>(qkv_b, off_w, off_b, biasx, wqkvx);
    }

    // 1) ln1: x -> h (fp16)
    layernorm_kernel<<<MROWS, 256>>>(x, n1w, n1b, h);

    // 2) qkvx = h @ [qkv_w;Weff]^T + bias : [16384, 2560] fp32 (valid 2400)
    {
        dim3 grid(QX / 256, MROWS / 128);
        hgemm_nt<0,float><<<grid, 256, HSM_BYTES>>>(h, wqkvx, biasx,
                                                    nullptr, 0, qkvx, QX,
                                                    CC, QKVW + NOFF);
    }

    // 3) deformable sampling + attention -> attn [16384, 768] fp16
    {
        dim3 grid(BQ * NT, NHEADS / 4);
        attn_kernel<<<grid, 128>>>(qkvx, refp, attn, Hp, Wp);
    }

    // 4) x1 = x + attn @ proj_w^T + proj_b -> out (fp32)
    {
        dim3 grid(CC / 256, MROWS / 128);
        hgemm_nt<2,float><<<grid, 256, HSM_BYTES>>>(attn, wproj, proj_b,
                                                    x, CC, out, CC, CC, CC);
    }

    // 5) ln2: out -> h (fp16)
    layernorm_kernel<<<MROWS, 256>>>(out, n2w, n2b, h);

    // 6) m = gelu(h @ fc1_w^T + fc1_b) -> mlp [16384, 3072] fp16
    {
        dim3 grid(HIDDEN / 256, MROWS / 128);
        hgemm_nt<1,__half><<<grid, 256, HSM_BYTES>>>(h, wfc1, fc1_b,
                                                     nullptr, 0, mlp, HIDDEN,
                                                     CC, HIDDEN);
    }

    // 7) out = out + mlp @ fc2_w^T + fc2_b (fp32)
    {
        dim3 grid(CC / 256, MROWS / 128);
        hgemm_nt<2,float><<<grid, 256, HSM_BYTES>>>(mlp, wfc2, fc2_b,
                                                    out, CC, out, CC,
                                                    HIDDEN, CC);
    }
}